// round 5
// baseline (speedup 1.0000x reference)
#include <cuda_runtime.h>
#include <cuda_bf16.h>

// out[n,h,d] = sum_j x[n,j,d] * FM[j+1,h] * Agg[0,j,h]
// (reference's sort/gap/code machinery telescopes to this linear map)
//
// R3: force MLP=4 with inline-PTX loads (ptxas was register-reusing and
// serializing the load batch: regs=36 in R1/R2 -> ~1 load in flight).

#define S_DIM 16
#define H_DIM 4
#define N_DIM 128
#define D_DIM 512

__device__ __forceinline__ float4 ldg_nc_v4(const float4* p) {
    float4 v;
    asm volatile("ld.global.nc.v4.f32 {%0,%1,%2,%3}, [%4];"
                 : "=f"(v.x), "=f"(v.y), "=f"(v.z), "=f"(v.w)
                 : "l"(p));
    return v;
}

__global__ void __launch_bounds__(128) cie_linear_kernel(
    const float* __restrict__ x,     // (N, S, D)
    const float* __restrict__ FM,    // (S+1, H)
    const float* __restrict__ Agg,   // (1, S, H)
    float* __restrict__ out)         // (N, H, D)
{
    __shared__ float W[S_DIM][H_DIM];
    const int tid = threadIdx.x;
    if (tid < S_DIM * H_DIM) {
        int j = tid / H_DIM, h = tid % H_DIM;
        W[j][h] = FM[(j + 1) * H_DIM + h] * Agg[j * H_DIM + h];
    }
    __syncthreads();

    const int b   = blockIdx.x;
    const int n   = b >> 2;            // 4 blocks per n
    const int dg  = b & 3;             // d-quarter
    const int jg  = tid & 3;           // j-group: j = jg*4 .. jg*4+3
    const int col = tid >> 2;          // 0..31
    const int d4  = dg * 32 + col;

    const float4* xp = reinterpret_cast<const float4*>(
        x + (size_t)n * S_DIM * D_DIM) + d4;

    // Four loads with un-reusable destination registers -> true MLP=4.
    float4 v0 = ldg_nc_v4(xp + (jg * 4 + 0) * (D_DIM / 4));
    float4 v1 = ldg_nc_v4(xp + (jg * 4 + 1) * (D_DIM / 4));
    float4 v2 = ldg_nc_v4(xp + (jg * 4 + 2) * (D_DIM / 4));
    float4 v3 = ldg_nc_v4(xp + (jg * 4 + 3) * (D_DIM / 4));

    float4 acc[H_DIM];
#pragma unroll
    for (int h = 0; h < H_DIM; h++) {
        const float w0 = W[jg * 4 + 0][h];
        const float w1 = W[jg * 4 + 1][h];
        const float w2 = W[jg * 4 + 2][h];
        const float w3 = W[jg * 4 + 3][h];
        float ax, ay, az, aw;
        ax = v0.x * w0; ay = v0.y * w0; az = v0.z * w0; aw = v0.w * w0;
        ax = fmaf(v1.x, w1, ax); ay = fmaf(v1.y, w1, ay);
        az = fmaf(v1.z, w1, az); aw = fmaf(v1.w, w1, aw);
        ax = fmaf(v2.x, w2, ax); ay = fmaf(v2.y, w2, ay);
        az = fmaf(v2.z, w2, az); aw = fmaf(v2.w, w2, aw);
        ax = fmaf(v3.x, w3, ax); ay = fmaf(v3.y, w3, ay);
        az = fmaf(v3.z, w3, az); aw = fmaf(v3.w, w3, aw);
        acc[h] = make_float4(ax, ay, az, aw);
    }

    // Reduce the 4 j-group partials across adjacent lanes (xor 1, then 2).
#pragma unroll
    for (int m = 1; m <= 2; m <<= 1) {
#pragma unroll
        for (int h = 0; h < H_DIM; h++) {
            acc[h].x += __shfl_xor_sync(0xffffffffu, acc[h].x, m);
            acc[h].y += __shfl_xor_sync(0xffffffffu, acc[h].y, m);
            acc[h].z += __shfl_xor_sync(0xffffffffu, acc[h].z, m);
            acc[h].w += __shfl_xor_sync(0xffffffffu, acc[h].w, m);
        }
    }

    if (jg == 0) {
        float4* op = reinterpret_cast<float4*>(
            out + (size_t)n * H_DIM * D_DIM) + d4;
#pragma unroll
        for (int h = 0; h < H_DIM; h++) op[h * (D_DIM / 4)] = acc[h];
    }
}

extern "C" void kernel_launch(void* const* d_in, const int* in_sizes, int n_in,
                              void* d_out, int out_size) {
    const float* x   = (const float*)d_in[0];   // (128,16,512) f32
    const float* FM  = (const float*)d_in[1];   // (17,4) f32
    const float* Agg = (const float*)d_in[2];   // (1,16,4) f32
    // d_in[3] = source_index, unused: the table gather telescopes away.
    float* out = (float*)d_out;                 // (128,4,512) f32

    cie_linear_kernel<<<N_DIM * 4, 128>>>(x, FM, Agg, out);
}

// round 6
// speedup vs baseline: 1.0385x; 1.0385x over previous
#include <cuda_runtime.h>
#include <cstdint>

// out[n,h,d] = sum_j x[n,j,d] * FM[j+1,h] * Agg[0,j,h]
// (reference's sort/gap/code machinery telescopes to this linear map)
//
// R5: replace per-thread LDG (register-capped MLP, 3 rounds stuck at
// ~700 GB/s) with one cp.async.bulk per block: 32 KB x[n] -> smem via the
// async engine (no register pressure), then conflict-free LDS compute.

#define S_DIM 16
#define H_DIM 4
#define N_DIM 128
#define D_DIM 512
#define TILE_BYTES (S_DIM * D_DIM * 4)   // 32768

__global__ void __launch_bounds__(128) cie_bulk_kernel(
    const float* __restrict__ x,     // (N, S, D)
    const float* __restrict__ FM,    // (S+1, H)
    const float* __restrict__ Agg,   // (1, S, H)
    float* __restrict__ out)         // (N, H, D)
{
    __shared__ alignas(128) float xs[S_DIM * D_DIM];   // 32 KB
    __shared__ float W[S_DIM][H_DIM];
    __shared__ alignas(8) uint64_t mbar;

    const int tid = threadIdx.x;
    const int n   = blockIdx.x;

    const uint32_t mbar_a = (uint32_t)__cvta_generic_to_shared(&mbar);
    const uint32_t xs_a   = (uint32_t)__cvta_generic_to_shared(xs);

    if (tid == 0) {
        asm volatile("mbarrier.init.shared.b64 [%0], 1;" :: "r"(mbar_a) : "memory");
    }
    __syncthreads();

    if (tid == 0) {
        asm volatile("mbarrier.arrive.expect_tx.shared.b64 _, [%0], %1;"
                     :: "r"(mbar_a), "r"((uint32_t)TILE_BYTES) : "memory");
        asm volatile(
            "cp.async.bulk.shared::cluster.global.mbarrier::complete_tx::bytes "
            "[%0], [%1], %2, [%3];"
            :: "r"(xs_a), "l"(x + (size_t)n * S_DIM * D_DIM),
               "r"((uint32_t)TILE_BYTES), "r"(mbar_a) : "memory");
    }

    // Overlap: build W while the bulk copy streams.
    if (tid < S_DIM * H_DIM) {
        int j = tid / H_DIM, h = tid % H_DIM;
        W[j][h] = FM[(j + 1) * H_DIM + h] * Agg[j * H_DIM + h];
    }
    __syncthreads();   // W visible to all

    // Wait for the bulk copy (phase parity 0).
    asm volatile(
        "{\n\t"
        ".reg .pred P;\n"
        "WAIT_%=:\n\t"
        "mbarrier.try_wait.parity.acquire.cta.shared::cta.b64 P, [%0], %1;\n\t"
        "@P bra DONE_%=;\n\t"
        "bra WAIT_%=;\n"
        "DONE_%=:\n\t"
        "}"
        :: "r"(mbar_a), "r"(0u) : "memory");

    // Compute: thread t owns d4 column t. Consecutive lanes -> consecutive
    // float4s -> conflict-free LDS.128.
    const float4* xs4 = reinterpret_cast<const float4*>(xs);

    float4 acc[H_DIM];
#pragma unroll
    for (int h = 0; h < H_DIM; h++) acc[h] = make_float4(0.f, 0.f, 0.f, 0.f);

#pragma unroll
    for (int j = 0; j < S_DIM; j++) {
        float4 v = xs4[j * (D_DIM / 4) + tid];
#pragma unroll
        for (int h = 0; h < H_DIM; h++) {
            const float w = W[j][h];
            acc[h].x = fmaf(v.x, w, acc[h].x);
            acc[h].y = fmaf(v.y, w, acc[h].y);
            acc[h].z = fmaf(v.z, w, acc[h].z);
            acc[h].w = fmaf(v.w, w, acc[h].w);
        }
    }

    float4* op = reinterpret_cast<float4*>(out + (size_t)n * H_DIM * D_DIM) + tid;
#pragma unroll
    for (int h = 0; h < H_DIM; h++) op[h * (D_DIM / 4)] = acc[h];
}

extern "C" void kernel_launch(void* const* d_in, const int* in_sizes, int n_in,
                              void* d_out, int out_size) {
    const float* x   = (const float*)d_in[0];   // (128,16,512) f32
    const float* FM  = (const float*)d_in[1];   // (17,4) f32
    const float* Agg = (const float*)d_in[2];   // (1,16,4) f32
    // d_in[3] = source_index, unused: the table gather telescopes away.
    float* out = (float*)d_out;                 // (128,4,512) f32

    cie_bulk_kernel<<<N_DIM, 128>>>(x, FM, Agg, out);
}